// round 13
// baseline (speedup 1.0000x reference)
#include <cuda_runtime.h>
#include <cuda_fp16.h>
#include <cstdint>

#define Bc  2
#define Tc  2048
#define Dc  1024
#define NHc 32
#define HDc 32
#define Mc  (Bc*Tc)   // 4096

// Scratch (allocation-free rule: __device__ globals). All fp16.
__device__ half g_xh[Mc*Dc];
__device__ half g_wqh[Dc*Dc];
__device__ half g_wkh[Dc*Dc];
__device__ half g_wvh[Dc*Dc];
__device__ half g_wph[Dc*Dc];
__device__ half g_q[Bc*NHc*Tc*HDc];   // [B,NH,T,HD] post rope*gain*scale*log2e
__device__ half g_k[Bc*NHc*Tc*HDc];   // [B,NH,T,HD] post rope
__device__ half g_vt[Bc*NHc*HDc*Tc];  // [B,NH,HD,T]  (transposed)
__device__ half g_y[Mc*Dc];           // attn out

// ---------------- helpers ----------------
__device__ __forceinline__ void mma_f16(float* c, const unsigned* a, const unsigned* b) {
    asm volatile(
        "mma.sync.aligned.m16n8k16.row.col.f32.f16.f16.f32 "
        "{%0,%1,%2,%3}, {%4,%5,%6,%7}, {%8,%9}, {%0,%1,%2,%3};"
        : "+f"(c[0]), "+f"(c[1]), "+f"(c[2]), "+f"(c[3])
        : "r"(a[0]), "r"(a[1]), "r"(a[2]), "r"(a[3]), "r"(b[0]), "r"(b[1]));
}
__device__ __forceinline__ void ldsm4(unsigned& r0, unsigned& r1, unsigned& r2,
                                      unsigned& r3, unsigned addr) {
    asm volatile("ldmatrix.sync.aligned.m8n8.x4.shared.b16 {%0,%1,%2,%3}, [%4];"
                 : "=r"(r0), "=r"(r1), "=r"(r2), "=r"(r3) : "r"(addr));
}
__device__ __forceinline__ void cp16(unsigned s, const void* g) {
    asm volatile("cp.async.cg.shared.global [%0], [%1], 16;" :: "r"(s), "l"(g));
}
#define CP_COMMIT()  asm volatile("cp.async.commit_group;")
#define CP_WAIT2()   asm volatile("cp.async.wait_group 2;")
#define CP_WAIT1()   asm volatile("cp.async.wait_group 1;")
#define CP_WAIT0()   asm volatile("cp.async.wait_group 0;")

// ---------------------------------------------------------------------------
// Prepass: fp32 -> fp16 (RN) for x and the 4 weights.
// ---------------------------------------------------------------------------
__global__ void prep_half(const float* __restrict__ x,  const float* __restrict__ wq,
                          const float* __restrict__ wk, const float* __restrict__ wv,
                          const float* __restrict__ wp) {
    const long NX = (long)Mc*Dc/4;
    const long NW = (long)Dc*Dc/4;
    long i = (long)blockIdx.x*blockDim.x + threadIdx.x;
    if (i >= NX + 4*NW) return;
    const float4* s; half2* d; long o;
    if (i < NX) { s = (const float4*)x + i; d = (half2*)g_xh; o = i; }
    else {
        long j = i - NX; int w = (int)(j / NW); o = j % NW;
        const float* sw = (w == 0) ? wq : (w == 1) ? wk : (w == 2) ? wv : wp;
        half* dw = (w == 0) ? g_wqh : (w == 1) ? g_wkh : (w == 2) ? g_wvh : g_wph;
        s = (const float4*)sw + o; d = (half2*)dw;
    }
    float4 v = *s;
    d[2*o]   = __floats2half2_rn(v.x, v.y);
    d[2*o+1] = __floats2half2_rn(v.z, v.w);
}

// GEMM core: 128x64 tile, Kstep 32, pitch 20 words/row, 4-stage ring.
#define PH   20
#define SAW  (128*PH)   // A stage words: 2560
#define SBW  (64*PH)    // B stage words: 1280
#define STGW (SAW+SBW)  // 3840 words = 15360 B per stage

// ---------------------------------------------------------------------------
// Fused QKV GEMM (fp16 MMA + ldmatrix) + RMSNorm + RoPE epilogue.
// 8 warps: wm = wid>>1 (32-row slab), wn = wid&1 (32-col slab = one head).
// ---------------------------------------------------------------------------
__global__ void __launch_bounds__(256, 3)
qkv_fused(const float* __restrict__ gain,
          const float* __restrict__ cosb,
          const float* __restrict__ sinb) {
    extern __shared__ unsigned smu[];
    const unsigned sm_u = (unsigned)__cvta_generic_to_shared(smu);

    const int z = blockIdx.z;
    const half* W = (z == 0) ? g_wqh : (z == 1) ? g_wkh : g_wvh;
    const int m0 = blockIdx.y * 128, n0 = blockIdx.x * 64;
    const int tid = threadIdx.x, lane = tid & 31, wid = tid >> 5;
    const int wm = wid >> 1, wn = wid & 1;

    float acc[2][4][4] = {};

    auto load_stage = [&](int st, int k0) {
        unsigned base = sm_u + (unsigned)st * STGW * 4;
        #pragma unroll
        for (int i = 0; i < 2; i++) {               // A: 128 rows x 4 chunks
            int idx = tid + i * 256;
            int row = idx >> 2, ci = idx & 3;
            cp16(base + (row*PH + ci*4)*4,
                 &g_xh[(size_t)(m0 + row)*Dc + k0 + ci*8]);
        }
        {                                           // B: 64 rows x 4 chunks
            int row = tid >> 2, ci = tid & 3;
            cp16(base + (SAW + row*PH + ci*4)*4,
                 &W[(size_t)(n0 + row)*Dc + k0 + ci*8]);
        }
        CP_COMMIT();
    };

    const int a_r  = lane & 15;
    const int a_ch = (lane >> 4) << 2;
    const int b_r  = lane & 7;
    const int b_nt = (lane >> 4) & 1;
    const int b_ch = ((lane >> 3) & 1) << 2;

    load_stage(0, 0); load_stage(1, 32); load_stage(2, 64);
    for (int ks = 0; ks < 32; ks++) {
        if (ks <= 29)      { CP_WAIT2(); }   // 3 pending -> oldest (ks) retired
        else if (ks == 30) { CP_WAIT1(); }
        else               { CP_WAIT0(); }
        __syncthreads();
        if (ks + 3 < 32) load_stage((ks + 3) & 3, (ks + 3) * 32);

        unsigned base = sm_u + (unsigned)(ks & 3) * STGW * 4;
        #pragma unroll
        for (int kk = 0; kk < 2; kk++) {
            unsigned af[2][4], bf[2][4];
            #pragma unroll
            for (int mt = 0; mt < 2; mt++) {
                int r = wm*32 + mt*16 + a_r;
                ldsm4(af[mt][0], af[mt][1], af[mt][2], af[mt][3],
                      base + (r*PH + kk*8 + a_ch)*4);
            }
            #pragma unroll
            for (int np = 0; np < 2; np++) {
                int n = wn*32 + np*16 + b_nt*8 + b_r;
                ldsm4(bf[np][0], bf[np][1], bf[np][2], bf[np][3],
                      base + (SAW + n*PH + kk*8 + b_ch)*4);
            }
            #pragma unroll
            for (int mt = 0; mt < 2; mt++)
                #pragma unroll
                for (int np = 0; np < 2; np++) {
                    mma_f16(acc[mt][np*2],   af[mt], &bf[np][0]);
                    mma_f16(acc[mt][np*2+1], af[mt], &bf[np][2]);
                }
        }
        __syncthreads();
    }

    const int h = (n0 >> 5) + wn;   // warp's 32-col slab == one head
    if (z == 2) {
        // V: store TRANSPOSED [B,NH,HD,T]
        #pragma unroll
        for (int mt = 0; mt < 2; mt++) {
            int r0 = m0 + wm*32 + mt*16 + (lane >> 2);
            int b = r0 >> 11, t = r0 & 2047;
            #pragma unroll
            for (int nt = 0; nt < 4; nt++) {
                int d = nt*8 + (lane & 3)*2;
                size_t base = ((size_t)((b*NHc + h)*HDc + d))*Tc;
                g_vt[base + t]          = __float2half_rn(acc[mt][nt][0]);
                g_vt[base + Tc + t]     = __float2half_rn(acc[mt][nt][1]);
                g_vt[base + t + 8]      = __float2half_rn(acc[mt][nt][2]);
                g_vt[base + Tc + t + 8] = __float2half_rn(acc[mt][nt][3]);
            }
        }
        return;
    }

    // q/k: RMSNorm (quad reduce) + RoPE (partner = nt^2).
    half2* out2 = (half2*)((z == 0) ? g_q : g_k);
    const float gn = (z == 0)
        ? gain[h] * 0.17677669529663687f * 1.4426950408889634f : 1.0f;
    #pragma unroll
    for (int mt = 0; mt < 2; mt++) {
        int r0 = m0 + wm*32 + mt*16 + (lane >> 2);
        int b = r0 >> 11, t0 = r0 & 2047;

        float ss0 = 0.f, ss1 = 0.f;
        #pragma unroll
        for (int nt = 0; nt < 4; nt++) {
            ss0 += acc[mt][nt][0]*acc[mt][nt][0] + acc[mt][nt][1]*acc[mt][nt][1];
            ss1 += acc[mt][nt][2]*acc[mt][nt][2] + acc[mt][nt][3]*acc[mt][nt][3];
        }
        ss0 += __shfl_xor_sync(0xffffffffu, ss0, 1);
        ss0 += __shfl_xor_sync(0xffffffffu, ss0, 2);
        ss1 += __shfl_xor_sync(0xffffffffu, ss1, 1);
        ss1 += __shfl_xor_sync(0xffffffffu, ss1, 2);
        float sc0 = rsqrtf(ss0 * (1.0f/HDc) + 1e-6f) * gn;
        float sc1 = rsqrtf(ss1 * (1.0f/HDc) + 1e-6f) * gn;

        float nv[4][4];
        #pragma unroll
        for (int nt = 0; nt < 4; nt++) {
            nv[nt][0] = acc[mt][nt][0]*sc0; nv[nt][1] = acc[mt][nt][1]*sc0;
            nv[nt][2] = acc[mt][nt][2]*sc1; nv[nt][3] = acc[mt][nt][3]*sc1;
        }
        #pragma unroll
        for (int nt = 0; nt < 4; nt++) {
            int d  = nt*8 + (lane & 3)*2;
            int dh = d & 15;
            float c00 = cosb[t0*16 + dh],     s00 = sinb[t0*16 + dh];
            float c01 = cosb[t0*16 + dh + 1], s01 = sinb[t0*16 + dh + 1];
            float c10 = cosb[(t0+8)*16 + dh],     s10 = sinb[(t0+8)*16 + dh];
            float c11 = cosb[(t0+8)*16 + dh + 1], s11 = sinb[(t0+8)*16 + dh + 1];
            float o0, o1, o2, o3;
            if (nt < 2) {
                o0 = nv[nt][0]*c00 - nv[nt^2][0]*s00;
                o1 = nv[nt][1]*c01 - nv[nt^2][1]*s01;
                o2 = nv[nt][2]*c10 - nv[nt^2][2]*s10;
                o3 = nv[nt][3]*c11 - nv[nt^2][3]*s11;
            } else {
                o0 = nv[nt][0]*c00 + nv[nt^2][0]*s00;
                o1 = nv[nt][1]*c01 + nv[nt^2][1]*s01;
                o2 = nv[nt][2]*c10 + nv[nt^2][2]*s10;
                o3 = nv[nt][3]*c11 + nv[nt^2][3]*s11;
            }
            size_t rowi = (size_t)((b*NHc + h)*Tc);
            out2[(rowi + t0)*16 + nt*4 + (lane & 3)]     = __floats2half2_rn(o0, o1);
            out2[(rowi + t0 + 8)*16 + nt*4 + (lane & 3)] = __floats2half2_rn(o2, o3);
        }
    }
}

// ---------------------------------------------------------------------------
// Output projection: d_out(fp32) = g_y @ Wproj^T.
// ---------------------------------------------------------------------------
__global__ void __launch_bounds__(256, 3)
proj_gemm(float* __restrict__ out) {
    extern __shared__ unsigned smu[];
    const unsigned sm_u = (unsigned)__cvta_generic_to_shared(smu);

    const int m0 = blockIdx.y * 128, n0 = blockIdx.x * 64;
    const int tid = threadIdx.x, lane = tid & 31, wid = tid >> 5;
    const int wm = wid >> 1, wn = wid & 1;

    float acc[2][4][4] = {};

    auto load_stage = [&](int st, int k0) {
        unsigned base = sm_u + (unsigned)st * STGW * 4;
        #pragma unroll
        for (int i = 0; i < 2; i++) {
            int idx = tid + i * 256;
            int row = idx >> 2, ci = idx & 3;
            cp16(base + (row*PH + ci*4)*4,
                 &g_y[(size_t)(m0 + row)*Dc + k0 + ci*8]);
        }
        {
            int row = tid >> 2, ci = tid & 3;
            cp16(base + (SAW + row*PH + ci*4)*4,
                 &g_wph[(size_t)(n0 + row)*Dc + k0 + ci*8]);
        }
        CP_COMMIT();
    };

    const int a_r  = lane & 15;
    const int a_ch = (lane >> 4) << 2;
    const int b_r  = lane & 7;
    const int b_nt = (lane >> 4) & 1;
    const int b_ch = ((lane >> 3) & 1) << 2;

    load_stage(0, 0); load_stage(1, 32); load_stage(2, 64);
    for (int ks = 0; ks < 32; ks++) {
        if (ks <= 29)      { CP_WAIT2(); }
        else if (ks == 30) { CP_WAIT1(); }
        else               { CP_WAIT0(); }
        __syncthreads();
        if (ks + 3 < 32) load_stage((ks + 3) & 3, (ks + 3) * 32);

        unsigned base = sm_u + (unsigned)(ks & 3) * STGW * 4;
        #pragma unroll
        for (int kk = 0; kk < 2; kk++) {
            unsigned af[2][4], bf[2][4];
            #pragma unroll
            for (int mt = 0; mt < 2; mt++) {
                int r = wm*32 + mt*16 + a_r;
                ldsm4(af[mt][0], af[mt][1], af[mt][2], af[mt][3],
                      base + (r*PH + kk*8 + a_ch)*4);
            }
            #pragma unroll
            for (int np = 0; np < 2; np++) {
                int n = wn*32 + np*16 + b_nt*8 + b_r;
                ldsm4(bf[np][0], bf[np][1], bf[np][2], bf[np][3],
                      base + (SAW + n*PH + kk*8 + b_ch)*4);
            }
            #pragma unroll
            for (int mt = 0; mt < 2; mt++)
                #pragma unroll
                for (int np = 0; np < 2; np++) {
                    mma_f16(acc[mt][np*2],   af[mt], &bf[np][0]);
                    mma_f16(acc[mt][np*2+1], af[mt], &bf[np][2]);
                }
        }
        __syncthreads();
    }

    #pragma unroll
    for (int mt = 0; mt < 2; mt++) {
        int r0 = m0 + wm*32 + mt*16 + (lane >> 2);
        #pragma unroll
        for (int nt = 0; nt < 4; nt++) {
            int c0 = n0 + wn*32 + nt*8 + (lane & 3)*2;
            *(float2*)&out[(size_t)r0*Dc + c0] =
                make_float2(acc[mt][nt][0], acc[mt][nt][1]);
            *(float2*)&out[(size_t)(r0+8)*Dc + c0] =
                make_float2(acc[mt][nt][2], acc[mt][nt][3]);
        }
    }
}

// ---------------------------------------------------------------------------
// Flash attention, fp16 mma.sync + ldmatrix (byte-identical to passing R8).
// ---------------------------------------------------------------------------
__global__ void __launch_bounds__(256, 2)
attn_mma() {
    extern __shared__ unsigned smu[];
    unsigned* Ps = smu;                   // 128 x 36  (4608 words)
    unsigned* Ks = smu + 4608;            // 2 x 64 x 20 (2560)
    unsigned* Vs = smu + 4608 + 2560;     // 2 x 32 x 36 (2304)
    const unsigned ps_u = (unsigned)__cvta_generic_to_shared(Ps);
    const unsigned ks_u = (unsigned)__cvta_generic_to_shared(Ks);
    const unsigned vs_u = (unsigned)__cvta_generic_to_shared(Vs);

    const int bh = blockIdx.y;
    const int q0 = ((int)gridDim.x - 1 - (int)blockIdx.x) * 128;  // longest first
    const half* kp  = g_k  + (size_t)bh * Tc * HDc;
    const half* vtp = g_vt + (size_t)bh * HDc * Tc;
    const int tid = threadIdx.x, lane = tid & 31, wid = tid >> 5;

    auto load_kv = [&](int buf, int k0) {
        cp16(ks_u + (buf*1280 + (tid>>2)*20 + (tid&3)*4)*4,
             &kp[(size_t)(k0 + (tid>>2))*HDc + (tid&3)*8]);
        cp16(vs_u + (buf*1152 + (tid>>3)*36 + (tid&7)*4)*4,
             &vtp[(size_t)(tid>>3)*Tc + k0 + (tid&7)*8]);
        CP_COMMIT();
    };

    load_kv(0, 0);

    const int lr = wid*16 + (lane >> 2);
    const int gr0 = q0 + lr, gr1 = gr0 + 8;

    const int a_r  = lane & 15;
    const int a_ch = (lane >> 4) << 2;
    const int b_r  = lane & 7;
    const int b_nt = (lane >> 4) & 1;
    const int b_ch = ((lane >> 3) & 1) << 2;

    unsigned qf[2][4];
    {
        const unsigned* qu = (const unsigned*)g_q + (size_t)bh * Tc * 16;
        #pragma unroll
        for (int kk = 0; kk < 2; kk++) {
            int cq = kk*8 + (lane & 3);
            qf[kk][0] = qu[(size_t)gr0*16 + cq];
            qf[kk][1] = qu[(size_t)gr1*16 + cq];
            qf[kk][2] = qu[(size_t)gr0*16 + cq + 4];
            qf[kk][3] = qu[(size_t)gr1*16 + cq + 4];
        }
    }

    float m_run[2] = {-1e30f, -1e30f};
    float l_run[2] = {0.f, 0.f};
    float o[4][4] = {};

    const int nkb = (q0 + 128) / 64;
    for (int kb = 0; kb < nkb; kb++) {
        const int k0 = kb * 64;
        const int buf = kb & 1;
        if (kb + 1 < nkb) { load_kv(buf ^ 1, (kb + 1) * 64); CP_WAIT1(); }
        else              { CP_WAIT0(); }
        __syncthreads();

        float s[8][4] = {};
        #pragma unroll
        for (int kk = 0; kk < 2; kk++) {
            #pragma unroll
            for (int np = 0; np < 4; np++) {
                unsigned bf[4];
                int n = np*16 + b_nt*8 + b_r;
                ldsm4(bf[0], bf[1], bf[2], bf[3],
                      ks_u + (buf*1280 + n*20 + kk*8 + b_ch)*4);
                mma_f16(s[np*2],   qf[kk], &bf[0]);
                mma_f16(s[np*2+1], qf[kk], &bf[2]);
            }
        }

        if (k0 + 63 > q0 + wid*16) {
            #pragma unroll
            for (int nt = 0; nt < 8; nt++) {
                int c0 = k0 + nt*8 + (lane & 3)*2;
                if (c0     > gr0) s[nt][0] = -1e30f;
                if (c0 + 1 > gr0) s[nt][1] = -1e30f;
                if (c0     > gr1) s[nt][2] = -1e30f;
                if (c0 + 1 > gr1) s[nt][3] = -1e30f;
            }
        }

        #pragma unroll
        for (int r = 0; r < 2; r++) {
            float mx = -1e30f;
            #pragma unroll
            for (int nt = 0; nt < 8; nt++)
                mx = fmaxf(mx, fmaxf(s[nt][2*r], s[nt][2*r+1]));
            mx = fmaxf(mx, __shfl_xor_sync(0xffffffffu, mx, 1));
            mx = fmaxf(mx, __shfl_xor_sync(0xffffffffu, mx, 2));
            float mn = fmaxf(m_run[r], mx);
            float corr = exp2f(m_run[r] - mn);
            float sum = 0.f;
            #pragma unroll
            for (int nt = 0; nt < 8; nt++) {
                float p0 = exp2f(s[nt][2*r]   - mn);
                float p1 = exp2f(s[nt][2*r+1] - mn);
                s[nt][2*r] = p0; s[nt][2*r+1] = p1;
                sum += p0 + p1;
            }
            sum += __shfl_xor_sync(0xffffffffu, sum, 1);
            sum += __shfl_xor_sync(0xffffffffu, sum, 2);
            l_run[r] = l_run[r]*corr + sum;
            m_run[r] = mn;
            #pragma unroll
            for (int nt = 0; nt < 4; nt++) {
                o[nt][2*r]   *= corr;
                o[nt][2*r+1] *= corr;
            }
        }

        #pragma unroll
        for (int nt = 0; nt < 8; nt++) {
            int pc = nt*4 + (lane & 3);
            *(half2*)&Ps[lr*36 + pc]     = __floats2half2_rn(s[nt][0], s[nt][1]);
            *(half2*)&Ps[(lr+8)*36 + pc] = __floats2half2_rn(s[nt][2], s[nt][3]);
        }
        __syncwarp();

        #pragma unroll
        for (int kk = 0; kk < 4; kk++) {
            unsigned af[4];
            {
                int r = wid*16 + a_r;
                ldsm4(af[0], af[1], af[2], af[3],
                      ps_u + (r*36 + kk*8 + a_ch)*4);
            }
            #pragma unroll
            for (int np = 0; np < 2; np++) {
                unsigned bv[4];
                int n = np*16 + b_nt*8 + b_r;
                ldsm4(bv[0], bv[1], bv[2], bv[3],
                      vs_u + (buf*1152 + n*36 + kk*8 + b_ch)*4);
                mma_f16(o[np*2],   af, &bv[0]);
                mma_f16(o[np*2+1], af, &bv[2]);
            }
        }
        __syncthreads();
    }

    const int b = bh / NHc, h = bh % NHc;
    const float inv0 = 1.0f / l_run[0];
    const float inv1 = 1.0f / l_run[1];
    half2* y2 = (half2*)g_y;
    #pragma unroll
    for (int nt = 0; nt < 4; nt++) {
        int pc = nt*4 + (lane & 3);
        y2[((size_t)(b*Tc + gr0))*512 + h*16 + pc] =
            __floats2half2_rn(o[nt][0]*inv0, o[nt][1]*inv0);
        y2[((size_t)(b*Tc + gr1))*512 + h*16 + pc] =
            __floats2half2_rn(o[nt][2]*inv1, o[nt][3]*inv1);
    }
}

extern "C" void kernel_launch(void* const* d_in, const int* in_sizes, int n_in,
                              void* d_out, int out_size) {
    const float* x    = (const float*)d_in[0];
    const float* Wq   = (const float*)d_in[1];
    const float* Wk   = (const float*)d_in[2];
    const float* Wv   = (const float*)d_in[3];
    const float* Wp   = (const float*)d_in[4];
    const float* gain = (const float*)d_in[5];
    const float* cosb = (const float*)d_in[6];
    const float* sinb = (const float*)d_in[7];

    const int gemm_smem = 4 * STGW * 4;                 // 61440 B
    const int attn_smem = (4608 + 2560 + 2304) * 4;     // 37888 B
    cudaFuncSetAttribute(qkv_fused, cudaFuncAttributeMaxDynamicSharedMemorySize, gemm_smem);
    cudaFuncSetAttribute(proj_gemm, cudaFuncAttributeMaxDynamicSharedMemorySize, gemm_smem);
    cudaFuncSetAttribute(attn_mma,  cudaFuncAttributeMaxDynamicSharedMemorySize, attn_smem);

    const long nprep = (long)Mc*Dc/4 + 4L*Dc*Dc/4;
    prep_half<<<(int)((nprep + 255)/256), 256>>>(x, Wq, Wk, Wv, Wp);
    qkv_fused<<<dim3(Dc/64, Mc/128, 3), 256, gemm_smem>>>(gain, cosb, sinb);
    attn_mma<<<dim3(Tc/128, Bc*NHc), 256, attn_smem>>>();
    proj_gemm<<<dim3(Dc/64, Mc/128), 256, gemm_smem>>>((float*)d_out);
}

// round 14
// speedup vs baseline: 1.0862x; 1.0862x over previous
#include <cuda_runtime.h>
#include <cuda_fp16.h>
#include <cstdint>

#define Bc  2
#define Tc  2048
#define Dc  1024
#define NHc 32
#define HDc 32
#define Mc  (Bc*Tc)   // 4096

// Scratch (allocation-free rule: __device__ globals). All fp16.
__device__ half g_xh[Mc*Dc];
__device__ half g_wqh[Dc*Dc];
__device__ half g_wkh[Dc*Dc];
__device__ half g_wvh[Dc*Dc];
__device__ half g_wph[Dc*Dc];
__device__ half g_q[Bc*NHc*Tc*HDc];   // [B,NH,T,HD] post rope*gain*scale*log2e
__device__ half g_k[Bc*NHc*Tc*HDc];   // [B,NH,T,HD] post rope
__device__ half g_vt[Bc*NHc*HDc*Tc];  // [B,NH,HD,T]  (transposed)
__device__ half g_y[Mc*Dc];           // attn out

// ---------------- helpers ----------------
__device__ __forceinline__ void mma_f16(float* c, const unsigned* a, const unsigned* b) {
    asm volatile(
        "mma.sync.aligned.m16n8k16.row.col.f32.f16.f16.f32 "
        "{%0,%1,%2,%3}, {%4,%5,%6,%7}, {%8,%9}, {%0,%1,%2,%3};"
        : "+f"(c[0]), "+f"(c[1]), "+f"(c[2]), "+f"(c[3])
        : "r"(a[0]), "r"(a[1]), "r"(a[2]), "r"(a[3]), "r"(b[0]), "r"(b[1]));
}
__device__ __forceinline__ void ldsm4(unsigned& r0, unsigned& r1, unsigned& r2,
                                      unsigned& r3, unsigned addr) {
    asm volatile("ldmatrix.sync.aligned.m8n8.x4.shared.b16 {%0,%1,%2,%3}, [%4];"
                 : "=r"(r0), "=r"(r1), "=r"(r2), "=r"(r3) : "r"(addr));
}
__device__ __forceinline__ void cp16(unsigned s, const void* g) {
    asm volatile("cp.async.cg.shared.global [%0], [%1], 16;" :: "r"(s), "l"(g));
}
__device__ __forceinline__ unsigned h2u(half2 h) {
    return *(unsigned*)&h;
}
#define CP_COMMIT()  asm volatile("cp.async.commit_group;")
#define CP_WAIT1()   asm volatile("cp.async.wait_group 1;")
#define CP_WAIT0()   asm volatile("cp.async.wait_group 0;")

// ---------------------------------------------------------------------------
// Prepass: fp32 -> fp16 (RN) for x and the 4 weights.
// ---------------------------------------------------------------------------
__global__ void prep_half(const float* __restrict__ x,  const float* __restrict__ wq,
                          const float* __restrict__ wk, const float* __restrict__ wv,
                          const float* __restrict__ wp) {
    const long NX = (long)Mc*Dc/4;
    const long NW = (long)Dc*Dc/4;
    long i = (long)blockIdx.x*blockDim.x + threadIdx.x;
    if (i >= NX + 4*NW) return;
    const float4* s; half2* d; long o;
    if (i < NX) { s = (const float4*)x + i; d = (half2*)g_xh; o = i; }
    else {
        long j = i - NX; int w = (int)(j / NW); o = j % NW;
        const float* sw = (w == 0) ? wq : (w == 1) ? wk : (w == 2) ? wv : wp;
        half* dw = (w == 0) ? g_wqh : (w == 1) ? g_wkh : (w == 2) ? g_wvh : g_wph;
        s = (const float4*)sw + o; d = (half2*)dw;
    }
    float4 v = *s;
    d[2*o]   = __floats2half2_rn(v.x, v.y);
    d[2*o+1] = __floats2half2_rn(v.z, v.w);
}

// GEMM core (R8 config): 128x128 tile, Kstep 32, pitch 20 words/row, 3 stages.
#define PH  20
#define STW (128*PH)   // 2560 words per stage per matrix

// ---------------------------------------------------------------------------
// Fused QKV GEMM (fp16 MMA + ldmatrix) + RMSNorm + RoPE epilogue.
// ---------------------------------------------------------------------------
__global__ void __launch_bounds__(256, 2)
qkv_fused(const float* __restrict__ gain,
          const float* __restrict__ cosb,
          const float* __restrict__ sinb) {
    extern __shared__ unsigned smu[];
    unsigned* As = smu;             // [3][2560]
    unsigned* Bs = smu + 3*STW;
    const unsigned as_u = (unsigned)__cvta_generic_to_shared(As);
    const unsigned bs_u = (unsigned)__cvta_generic_to_shared(Bs);

    const int z = blockIdx.z;
    const half* W = (z == 0) ? g_wqh : (z == 1) ? g_wkh : g_wvh;
    const int m0 = blockIdx.y * 128, n0 = blockIdx.x * 128;
    const int tid = threadIdx.x, lane = tid & 31, wid = tid >> 5;
    const int wm = wid >> 2, wn = wid & 3;

    float acc[4][4][4] = {};

    auto load_stage = [&](int buf, int k0) {
        #pragma unroll
        for (int i = 0; i < 2; i++) {
            int idx = tid + i * 256;
            int row = idx >> 2, ci = idx & 3;
            cp16(as_u + (buf*STW + row*PH + ci*4)*4,
                 &g_xh[(size_t)(m0 + row)*Dc + k0 + ci*8]);
            cp16(bs_u + (buf*STW + row*PH + ci*4)*4,
                 &W[(size_t)(n0 + row)*Dc + k0 + ci*8]);
        }
        CP_COMMIT();
    };

    const int a_r  = lane & 15;
    const int a_ch = (lane >> 4) << 2;
    const int b_r  = lane & 7;
    const int b_nt = (lane >> 4) & 1;
    const int b_ch = ((lane >> 3) & 1) << 2;

    load_stage(0, 0);
    load_stage(1, 32);
    int buf = 0;
    for (int ks = 0; ks < 32; ks++) {
        if (ks == 31) { CP_WAIT0(); } else { CP_WAIT1(); }
        __syncthreads();
        if (ks + 2 < 32) {
            int nb = buf + 2; if (nb >= 3) nb -= 3;
            load_stage(nb, (ks + 2) * 32);
        }
        #pragma unroll
        for (int kk = 0; kk < 2; kk++) {
            unsigned af[4][4], bf[2][4];
            #pragma unroll
            for (int mt = 0; mt < 4; mt++) {
                int r = wm*64 + mt*16 + a_r;
                ldsm4(af[mt][0], af[mt][1], af[mt][2], af[mt][3],
                      as_u + (buf*STW + r*PH + kk*8 + a_ch)*4);
            }
            #pragma unroll
            for (int np = 0; np < 2; np++) {
                int n = wn*32 + np*16 + b_nt*8 + b_r;
                ldsm4(bf[np][0], bf[np][1], bf[np][2], bf[np][3],
                      bs_u + (buf*STW + n*PH + kk*8 + b_ch)*4);
            }
            #pragma unroll
            for (int mt = 0; mt < 4; mt++)
                #pragma unroll
                for (int np = 0; np < 2; np++) {
                    mma_f16(acc[mt][np*2],   af[mt], &bf[np][0]);
                    mma_f16(acc[mt][np*2+1], af[mt], &bf[np][2]);
                }
        }
        if (++buf >= 3) buf = 0;
    }

    const int h = (n0 >> 5) + wn;   // warp's 32-col slab == one head
    if (z == 2) {
        // V: store TRANSPOSED [B,NH,HD,T]
        #pragma unroll
        for (int mt = 0; mt < 4; mt++) {
            int r0 = m0 + wm*64 + mt*16 + (lane >> 2);
            int b = r0 >> 11, t = r0 & 2047;
            #pragma unroll
            for (int nt = 0; nt < 4; nt++) {
                int d = nt*8 + (lane & 3)*2;
                size_t base = ((size_t)((b*NHc + h)*HDc + d))*Tc;
                g_vt[base + t]          = __float2half_rn(acc[mt][nt][0]);
                g_vt[base + Tc + t]     = __float2half_rn(acc[mt][nt][1]);
                g_vt[base + t + 8]      = __float2half_rn(acc[mt][nt][2]);
                g_vt[base + Tc + t + 8] = __float2half_rn(acc[mt][nt][3]);
            }
        }
        return;
    }

    // q/k: RMSNorm (quad reduce) + RoPE (partner = nt^2).
    half2* out2 = (half2*)((z == 0) ? g_q : g_k);
    const float gn = (z == 0)
        ? gain[h] * 0.17677669529663687f * 1.4426950408889634f : 1.0f;
    #pragma unroll
    for (int mt = 0; mt < 4; mt++) {
        int r0 = m0 + wm*64 + mt*16 + (lane >> 2);
        int b = r0 >> 11, t0 = r0 & 2047;

        float ss0 = 0.f, ss1 = 0.f;
        #pragma unroll
        for (int nt = 0; nt < 4; nt++) {
            ss0 += acc[mt][nt][0]*acc[mt][nt][0] + acc[mt][nt][1]*acc[mt][nt][1];
            ss1 += acc[mt][nt][2]*acc[mt][nt][2] + acc[mt][nt][3]*acc[mt][nt][3];
        }
        ss0 += __shfl_xor_sync(0xffffffffu, ss0, 1);
        ss0 += __shfl_xor_sync(0xffffffffu, ss0, 2);
        ss1 += __shfl_xor_sync(0xffffffffu, ss1, 1);
        ss1 += __shfl_xor_sync(0xffffffffu, ss1, 2);
        float sc0 = rsqrtf(ss0 * (1.0f/HDc) + 1e-6f) * gn;
        float sc1 = rsqrtf(ss1 * (1.0f/HDc) + 1e-6f) * gn;

        float nv[4][4];
        #pragma unroll
        for (int nt = 0; nt < 4; nt++) {
            nv[nt][0] = acc[mt][nt][0]*sc0; nv[nt][1] = acc[mt][nt][1]*sc0;
            nv[nt][2] = acc[mt][nt][2]*sc1; nv[nt][3] = acc[mt][nt][3]*sc1;
        }
        #pragma unroll
        for (int nt = 0; nt < 4; nt++) {
            int d  = nt*8 + (lane & 3)*2;
            int dh = d & 15;
            float c00 = cosb[t0*16 + dh],     s00 = sinb[t0*16 + dh];
            float c01 = cosb[t0*16 + dh + 1], s01 = sinb[t0*16 + dh + 1];
            float c10 = cosb[(t0+8)*16 + dh],     s10 = sinb[(t0+8)*16 + dh];
            float c11 = cosb[(t0+8)*16 + dh + 1], s11 = sinb[(t0+8)*16 + dh + 1];
            float o0, o1, o2, o3;
            if (nt < 2) {
                o0 = nv[nt][0]*c00 - nv[nt^2][0]*s00;
                o1 = nv[nt][1]*c01 - nv[nt^2][1]*s01;
                o2 = nv[nt][2]*c10 - nv[nt^2][2]*s10;
                o3 = nv[nt][3]*c11 - nv[nt^2][3]*s11;
            } else {
                o0 = nv[nt][0]*c00 + nv[nt^2][0]*s00;
                o1 = nv[nt][1]*c01 + nv[nt^2][1]*s01;
                o2 = nv[nt][2]*c10 + nv[nt^2][2]*s10;
                o3 = nv[nt][3]*c11 + nv[nt^2][3]*s11;
            }
            size_t rowi = (size_t)((b*NHc + h)*Tc);
            out2[(rowi + t0)*16 + nt*4 + (lane & 3)]     = __floats2half2_rn(o0, o1);
            out2[(rowi + t0 + 8)*16 + nt*4 + (lane & 3)] = __floats2half2_rn(o2, o3);
        }
    }
}

// ---------------------------------------------------------------------------
// Output projection: d_out(fp32) = g_y @ Wproj^T, fp16 MMA + ldmatrix.
// ---------------------------------------------------------------------------
__global__ void __launch_bounds__(256, 2)
proj_gemm(float* __restrict__ out) {
    extern __shared__ unsigned smu[];
    unsigned* As = smu;
    unsigned* Bs = smu + 3*STW;
    const unsigned as_u = (unsigned)__cvta_generic_to_shared(As);
    const unsigned bs_u = (unsigned)__cvta_generic_to_shared(Bs);

    const int m0 = blockIdx.y * 128, n0 = blockIdx.x * 128;
    const int tid = threadIdx.x, lane = tid & 31, wid = tid >> 5;
    const int wm = wid >> 2, wn = wid & 3;

    float acc[4][4][4] = {};

    auto load_stage = [&](int buf, int k0) {
        #pragma unroll
        for (int i = 0; i < 2; i++) {
            int idx = tid + i * 256;
            int row = idx >> 2, ci = idx & 3;
            cp16(as_u + (buf*STW + row*PH + ci*4)*4,
                 &g_y[(size_t)(m0 + row)*Dc + k0 + ci*8]);
            cp16(bs_u + (buf*STW + row*PH + ci*4)*4,
                 &g_wph[(size_t)(n0 + row)*Dc + k0 + ci*8]);
        }
        CP_COMMIT();
    };

    const int a_r  = lane & 15;
    const int a_ch = (lane >> 4) << 2;
    const int b_r  = lane & 7;
    const int b_nt = (lane >> 4) & 1;
    const int b_ch = ((lane >> 3) & 1) << 2;

    load_stage(0, 0);
    load_stage(1, 32);
    int buf = 0;
    for (int ks = 0; ks < 32; ks++) {
        if (ks == 31) { CP_WAIT0(); } else { CP_WAIT1(); }
        __syncthreads();
        if (ks + 2 < 32) {
            int nb = buf + 2; if (nb >= 3) nb -= 3;
            load_stage(nb, (ks + 2) * 32);
        }
        #pragma unroll
        for (int kk = 0; kk < 2; kk++) {
            unsigned af[4][4], bf[2][4];
            #pragma unroll
            for (int mt = 0; mt < 4; mt++) {
                int r = wm*64 + mt*16 + a_r;
                ldsm4(af[mt][0], af[mt][1], af[mt][2], af[mt][3],
                      as_u + (buf*STW + r*PH + kk*8 + a_ch)*4);
            }
            #pragma unroll
            for (int np = 0; np < 2; np++) {
                int n = wn*32 + np*16 + b_nt*8 + b_r;
                ldsm4(bf[np][0], bf[np][1], bf[np][2], bf[np][3],
                      bs_u + (buf*STW + n*PH + kk*8 + b_ch)*4);
            }
            #pragma unroll
            for (int mt = 0; mt < 4; mt++)
                #pragma unroll
                for (int np = 0; np < 2; np++) {
                    mma_f16(acc[mt][np*2],   af[mt], &bf[np][0]);
                    mma_f16(acc[mt][np*2+1], af[mt], &bf[np][2]);
                }
        }
        if (++buf >= 3) buf = 0;
    }

    #pragma unroll
    for (int mt = 0; mt < 4; mt++) {
        int r0 = m0 + wm*64 + mt*16 + (lane >> 2);
        #pragma unroll
        for (int nt = 0; nt < 4; nt++) {
            int c0 = n0 + wn*32 + nt*8 + (lane & 3)*2;
            *(float2*)&out[(size_t)r0*Dc + c0] =
                make_float2(acc[mt][nt][0], acc[mt][nt][1]);
            *(float2*)&out[(size_t)(r0+8)*Dc + c0] =
                make_float2(acc[mt][nt][2], acc[mt][nt][3]);
        }
    }
}

// ---------------------------------------------------------------------------
// Flash attention, fp16 mma.sync + ldmatrix, REGISTER-RESIDENT P.
// The S C-fragment IS the PV A-fragment; no P smem round-trip.
// ---------------------------------------------------------------------------
__global__ void __launch_bounds__(256, 2)
attn_mma() {
    extern __shared__ unsigned smu[];
    unsigned* Ks = smu;                   // 2 x 64 x 20 (2560)
    unsigned* Vs = smu + 2560;            // 2 x 32 x 36 (2304)
    const unsigned ks_u = (unsigned)__cvta_generic_to_shared(Ks);
    const unsigned vs_u = (unsigned)__cvta_generic_to_shared(Vs);

    const int bh = blockIdx.y;
    const int q0 = ((int)gridDim.x - 1 - (int)blockIdx.x) * 128;  // longest first
    const half* kp  = g_k  + (size_t)bh * Tc * HDc;
    const half* vtp = g_vt + (size_t)bh * HDc * Tc;
    const int tid = threadIdx.x, lane = tid & 31, wid = tid >> 5;

    auto load_kv = [&](int buf, int k0) {
        cp16(ks_u + (buf*1280 + (tid>>2)*20 + (tid&3)*4)*4,
             &kp[(size_t)(k0 + (tid>>2))*HDc + (tid&3)*8]);
        cp16(vs_u + (buf*1152 + (tid>>3)*36 + (tid&7)*4)*4,
             &vtp[(size_t)(tid>>3)*Tc + k0 + (tid&7)*8]);
        CP_COMMIT();
    };

    load_kv(0, 0);

    const int lr = wid*16 + (lane >> 2);
    const int gr0 = q0 + lr, gr1 = gr0 + 8;

    const int b_r  = lane & 7;
    const int b_nt = (lane >> 4) & 1;
    const int b_ch = ((lane >> 3) & 1) << 2;

    unsigned qf[2][4];
    {
        const unsigned* qu = (const unsigned*)g_q + (size_t)bh * Tc * 16;
        #pragma unroll
        for (int kk = 0; kk < 2; kk++) {
            int cq = kk*8 + (lane & 3);
            qf[kk][0] = qu[(size_t)gr0*16 + cq];
            qf[kk][1] = qu[(size_t)gr1*16 + cq];
            qf[kk][2] = qu[(size_t)gr0*16 + cq + 4];
            qf[kk][3] = qu[(size_t)gr1*16 + cq + 4];
        }
    }

    float m_run[2] = {-1e30f, -1e30f};
    float l_run[2] = {0.f, 0.f};
    float o[4][4] = {};

    const int nkb = (q0 + 128) / 64;
    for (int kb = 0; kb < nkb; kb++) {
        const int k0 = kb * 64;
        const int buf = kb & 1;
        if (kb + 1 < nkb) { load_kv(buf ^ 1, (kb + 1) * 64); CP_WAIT1(); }
        else              { CP_WAIT0(); }
        __syncthreads();

        float s[8][4] = {};
        #pragma unroll
        for (int kk = 0; kk < 2; kk++) {
            #pragma unroll
            for (int np = 0; np < 4; np++) {
                unsigned bf[4];
                int n = np*16 + b_nt*8 + b_r;
                ldsm4(bf[0], bf[1], bf[2], bf[3],
                      ks_u + (buf*1280 + n*20 + kk*8 + b_ch)*4);
                mma_f16(s[np*2],   qf[kk], &bf[0]);
                mma_f16(s[np*2+1], qf[kk], &bf[2]);
            }
        }

        if (k0 + 63 > q0 + wid*16) {   // causal mask
            #pragma unroll
            for (int nt = 0; nt < 8; nt++) {
                int c0 = k0 + nt*8 + (lane & 3)*2;
                if (c0     > gr0) s[nt][0] = -1e30f;
                if (c0 + 1 > gr0) s[nt][1] = -1e30f;
                if (c0     > gr1) s[nt][2] = -1e30f;
                if (c0 + 1 > gr1) s[nt][3] = -1e30f;
            }
        }

        // online softmax, base-2
        #pragma unroll
        for (int r = 0; r < 2; r++) {
            float mx = -1e30f;
            #pragma unroll
            for (int nt = 0; nt < 8; nt++)
                mx = fmaxf(mx, fmaxf(s[nt][2*r], s[nt][2*r+1]));
            mx = fmaxf(mx, __shfl_xor_sync(0xffffffffu, mx, 1));
            mx = fmaxf(mx, __shfl_xor_sync(0xffffffffu, mx, 2));
            float mn = fmaxf(m_run[r], mx);
            float corr = exp2f(m_run[r] - mn);
            float sum = 0.f;
            #pragma unroll
            for (int nt = 0; nt < 8; nt++) {
                float p0 = exp2f(s[nt][2*r]   - mn);
                float p1 = exp2f(s[nt][2*r+1] - mn);
                s[nt][2*r] = p0; s[nt][2*r+1] = p1;
                sum += p0 + p1;
            }
            sum += __shfl_xor_sync(0xffffffffu, sum, 1);
            sum += __shfl_xor_sync(0xffffffffu, sum, 2);
            l_run[r] = l_run[r]*corr + sum;
            m_run[r] = mn;
            #pragma unroll
            for (int nt = 0; nt < 4; nt++) {
                o[nt][2*r]   *= corr;
                o[nt][2*r+1] *= corr;
            }
        }

        // O += P @ V : P A-fragment built directly from S C-fragments.
        #pragma unroll
        for (int kk = 0; kk < 4; kk++) {
            unsigned af[4];
            af[0] = h2u(__floats2half2_rn(s[2*kk][0],   s[2*kk][1]));
            af[1] = h2u(__floats2half2_rn(s[2*kk][2],   s[2*kk][3]));
            af[2] = h2u(__floats2half2_rn(s[2*kk+1][0], s[2*kk+1][1]));
            af[3] = h2u(__floats2half2_rn(s[2*kk+1][2], s[2*kk+1][3]));
            #pragma unroll
            for (int np = 0; np < 2; np++) {
                unsigned bv[4];
                int n = np*16 + b_nt*8 + b_r;
                ldsm4(bv[0], bv[1], bv[2], bv[3],
                      vs_u + (buf*1152 + n*36 + kk*8 + b_ch)*4);
                mma_f16(o[np*2],   af, &bv[0]);
                mma_f16(o[np*2+1], af, &bv[2]);
            }
        }
        __syncthreads();
    }

    const int b = bh / NHc, h = bh % NHc;
    const float inv0 = 1.0f / l_run[0];
    const float inv1 = 1.0f / l_run[1];
    half2* y2 = (half2*)g_y;
    #pragma unroll
    for (int nt = 0; nt < 4; nt++) {
        int pc = nt*4 + (lane & 3);
        y2[((size_t)(b*Tc + gr0))*512 + h*16 + pc] =
            __floats2half2_rn(o[nt][0]*inv0, o[nt][1]*inv0);
        y2[((size_t)(b*Tc + gr1))*512 + h*16 + pc] =
            __floats2half2_rn(o[nt][2]*inv1, o[nt][3]*inv1);
    }
}

extern "C" void kernel_launch(void* const* d_in, const int* in_sizes, int n_in,
                              void* d_out, int out_size) {
    const float* x    = (const float*)d_in[0];
    const float* Wq   = (const float*)d_in[1];
    const float* Wk   = (const float*)d_in[2];
    const float* Wv   = (const float*)d_in[3];
    const float* Wp   = (const float*)d_in[4];
    const float* gain = (const float*)d_in[5];
    const float* cosb = (const float*)d_in[6];
    const float* sinb = (const float*)d_in[7];

    const int gemm_smem = 6 * STW * 4;            // 61440 B
    const int attn_smem = (2560 + 2304) * 4;      // 19456 B
    cudaFuncSetAttribute(qkv_fused, cudaFuncAttributeMaxDynamicSharedMemorySize, gemm_smem);
    cudaFuncSetAttribute(proj_gemm, cudaFuncAttributeMaxDynamicSharedMemorySize, gemm_smem);
    cudaFuncSetAttribute(attn_mma,  cudaFuncAttributeMaxDynamicSharedMemorySize, attn_smem);

    const long nprep = (long)Mc*Dc/4 + 4L*Dc*Dc/4;
    prep_half<<<(int)((nprep + 255)/256), 256>>>(x, Wq, Wk, Wv, Wp);
    qkv_fused<<<dim3(Dc/128, Mc/128, 3), 256, gemm_smem>>>(gain, cosb, sinb);
    attn_mma<<<dim3(Tc/128, Bc*NHc), 256, attn_smem>>>();
    proj_gemm<<<dim3(Dc/128, Mc/128), 256, gemm_smem>>>((float*)d_out);
}